// round 12
// baseline (speedup 1.0000x reference)
#include <cuda_runtime.h>
#include <cuda_fp16.h>
#include <cstdint>

// Problem constants
#define T_LEN 1024
#define B_SZ 2
#define E_DIM 1024
#define H_NUM 16
#define D_DIM 64
#define TB (T_LEN * B_SZ)          // 2048
#define CH 128                     // chunk length
#define NC (T_LEN / CH)            // 8 chunks
#define BHN (B_SZ * H_NUM)         // 32 head-batches
#define SCALE_ATT 0.125f           // 1/sqrt(64)

typedef __half hf;

// fp16 planes (device globals; no allocation allowed)
__device__ __align__(16) hf g_xh[3 * TB * E_DIM];
__device__ __align__(16) hf g_xl[3 * TB * E_DIM];
__device__ __align__(16) hf g_wh[4 * E_DIM * E_DIM];   // weights: hi only
__device__ __align__(16) hf g_ah[TB * E_DIM];          // attn out (t*B+b, e)
__device__ __align__(16) hf g_al[TB * E_DIM];
// (b,h,t,d) planes for attention
__device__ __align__(16) hf g_qh[BHN * T_LEN * D_DIM];
__device__ __align__(16) hf g_ql[BHN * T_LEN * D_DIM];
__device__ __align__(16) hf g_kh[BHN * T_LEN * D_DIM];
__device__ __align__(16) hf g_kl[BHN * T_LEN * D_DIM];
__device__ __align__(16) hf g_vh[BHN * T_LEN * D_DIM];
__device__ __align__(16) hf g_vl[BHN * T_LEN * D_DIM];
// exclusive-prefix S plane (hi only; k rows, v cols, per chunk)
__device__ __align__(16) hf g_sh[BHN * NC * D_DIM * D_DIM];

// ---- mma.sync helpers --------------------------------------------------------
__device__ __forceinline__ uint32_t smem_u32(const void* p) {
    uint32_t a;
    asm("{ .reg .u64 t; cvta.to.shared.u64 t, %1; cvt.u32.u64 %0, t; }"
        : "=r"(a) : "l"(p));
    return a;
}
__device__ __forceinline__ void cp16(uint32_t dst, const void* src) {
    asm volatile("cp.async.ca.shared.global [%0], [%1], 16;"
                 :: "r"(dst), "l"(src) : "memory");
}
#define CP_COMMIT() asm volatile("cp.async.commit_group;" ::: "memory")
#define CP_WAIT(n)  asm volatile("cp.async.wait_group %0;" :: "n"(n) : "memory")

__device__ __forceinline__ void ldm_x4(uint32_t* r, uint32_t addr) {
    asm volatile("ldmatrix.sync.aligned.m8n8.x4.shared.b16 {%0,%1,%2,%3}, [%4];"
                 : "=r"(r[0]), "=r"(r[1]), "=r"(r[2]), "=r"(r[3]) : "r"(addr));
}
__device__ __forceinline__ void ldm_x4t(uint32_t* r, uint32_t addr) {
    asm volatile("ldmatrix.sync.aligned.m8n8.x4.trans.shared.b16 {%0,%1,%2,%3}, [%4];"
                 : "=r"(r[0]), "=r"(r[1]), "=r"(r[2]), "=r"(r[3]) : "r"(addr));
}
__device__ __forceinline__ void ldm_x2t(uint32_t* r, uint32_t addr) {
    asm volatile("ldmatrix.sync.aligned.m8n8.x2.trans.shared.b16 {%0,%1}, [%2];"
                 : "=r"(r[0]), "=r"(r[1]) : "r"(addr));
}
__device__ __forceinline__ void mma_hf(float* c, const uint32_t* a, const uint32_t* b) {
    asm volatile(
        "mma.sync.aligned.m16n8k16.row.col.f32.f16.f16.f32 "
        "{%0,%1,%2,%3}, {%4,%5,%6,%7}, {%8,%9}, {%0,%1,%2,%3};"
        : "+f"(c[0]), "+f"(c[1]), "+f"(c[2]), "+f"(c[3])
        : "r"(a[0]), "r"(a[1]), "r"(a[2]), "r"(a[3]), "r"(b[0]), "r"(b[1]));
}
__device__ __forceinline__ uint32_t pk2(float lo, float hi) {
    __half2 t = __floats2half2_rn(lo, hi);
    return *(uint32_t*)&t;
}
__device__ __forceinline__ void split4(float4 x, uint2& H, uint2& L) {
    union { hf b[4]; uint2 u; } Hu, Lu;
    Hu.b[0] = __float2half_rn(x.x); Lu.b[0] = __float2half_rn(x.x - __half2float(Hu.b[0]));
    Hu.b[1] = __float2half_rn(x.y); Lu.b[1] = __float2half_rn(x.y - __half2float(Hu.b[1]));
    Hu.b[2] = __float2half_rn(x.z); Lu.b[2] = __float2half_rn(x.z - __half2float(Hu.b[2]));
    Hu.b[3] = __float2half_rn(x.w); Lu.b[3] = __float2half_rn(x.w - __half2float(Hu.b[3]));
    H = Hu.u; L = Lu.u;
}
__device__ __forceinline__ uint2 hi4(float4 x) {
    union { hf b[4]; uint2 u; } Hu;
    Hu.b[0] = __float2half_rn(x.x);
    Hu.b[1] = __float2half_rn(x.y);
    Hu.b[2] = __float2half_rn(x.z);
    Hu.b[3] = __float2half_rn(x.w);
    return Hu.u;
}

// ---------------------------------------------------------------------------
// Fused split: activations -> hi/lo, weights -> hi only. 4 float4 / thread.
// ---------------------------------------------------------------------------
#define ACT_F4 (TB * E_DIM / 4)            // 524288
#define W_F4 (E_DIM * E_DIM / 4)           // 262144
#define SPLIT_BLOCKS ((3 * ACT_F4 + 4 * W_F4) / 1024)   // 2560

__global__ __launch_bounds__(256) void split_fused(
    const float* __restrict__ q, const float* __restrict__ k,
    const float* __restrict__ v, const float* __restrict__ ipw,
    const float* __restrict__ opw)
{
    const int blk = blockIdx.x;
    const int tid = threadIdx.x;
    const size_t g0 = (size_t)blk * 1024;

    if (blk < 1536) {
        const int z = blk >> 9;
        const float* src = (z == 0) ? q : ((z == 1) ? k : v);
        const size_t local0 = g0 - (size_t)z * ACT_F4;
        hf* hi = g_xh + (size_t)z * TB * E_DIM;
        hf* lo = g_xl + (size_t)z * TB * E_DIM;
        float4 x[4];
        #pragma unroll
        for (int u = 0; u < 4; ++u)
            x[u] = ((const float4*)src)[local0 + tid + 256 * u];
        #pragma unroll
        for (int u = 0; u < 4; ++u) {
            uint2 H, L;
            split4(x[u], H, L);
            const size_t o = (local0 + tid + 256 * u) * 4;
            *(uint2*)(hi + o) = H;
            *(uint2*)(lo + o) = L;
        }
    } else {
        const float* src;
        size_t local0;
        hf* hi;
        if (blk < 2304) {
            src = ipw;
            local0 = g0 - (size_t)3 * ACT_F4;
            hi = g_wh;
        } else {
            src = opw;
            local0 = g0 - (size_t)3 * ACT_F4 - (size_t)3 * W_F4;
            hi = g_wh + (size_t)3 * E_DIM * E_DIM;
        }
        float4 x[4];
        #pragma unroll
        for (int u = 0; u < 4; ++u)
            x[u] = ((const float4*)src)[local0 + tid + 256 * u];
        #pragma unroll
        for (int u = 0; u < 4; ++u) {
            const size_t o = (local0 + tid + 256 * u) * 4;
            *(uint2*)(hi + o) = hi4(x[u]);
        }
    }
}

// ---------------------------------------------------------------------------
// GEMM mainloop: D(128x128) = A @ B^T.  2-term fp16: Ah*Bh + Al*Bh.
// 2-stage cp.async pipeline (R9-proven config; GEMM is mma-issue-bound).
// ---------------------------------------------------------------------------
#define KC 32
#define ROWB 80
#define TILE_BYTES (128 * ROWB)
#define STAGE_BYTES (3 * TILE_BYTES)       // 30720 (Ah|Al|Bh)
#define GEMM_SMEM 67584                    // max(2*STAGE_BYTES, 128*132*4)
#define NSTG (E_DIM / KC)                  // 32

__device__ __forceinline__ void mma_mainloop(
    const hf* __restrict__ Ah, const hf* __restrict__ Al,
    const hf* __restrict__ Bh,
    int m0, int n0, char* smem)
{
    const int tid = threadIdx.x, lane = tid & 31, wid = tid >> 5;
    const int wr = wid >> 2, wc = wid & 3;
    const uint32_t smb = smem_u32(smem);

    const hf* Ahb = Ah + (size_t)m0 * E_DIM;
    const hf* Alb = Al + (size_t)m0 * E_DIM;
    const hf* Bhb = Bh + (size_t)n0 * E_DIM;

    float acc[4][4][4];
    #pragma unroll
    for (int a = 0; a < 4; ++a)
        #pragma unroll
        for (int b = 0; b < 4; ++b)
            #pragma unroll
            for (int c = 0; c < 4; ++c) acc[a][b][c] = 0.f;

    auto issue = [&](int s) {
        const uint32_t db = smb + (s & 1) * STAGE_BYTES;
        #pragma unroll
        for (int u = 0; u < 2; ++u) {
            const int ci = tid + 256 * u;
            const int row = ci >> 2, kc = ci & 3;
            const uint32_t doff = row * ROWB + kc * 16;
            const size_t soff = (size_t)row * E_DIM + s * KC + kc * 8;
            cp16(db + doff,                  Ahb + soff);
            cp16(db + TILE_BYTES + doff,     Alb + soff);
            cp16(db + 2 * TILE_BYTES + doff, Bhb + soff);
        }
        CP_COMMIT();
    };

    const int aRow = lane & 15;
    const int aColB = (lane >> 4) * 16;

    issue(0);
    issue(1);

    for (int s = 0; s < NSTG; ++s) {
        CP_WAIT(1);
        __syncthreads();

        const uint32_t db = smb + (s & 1) * STAGE_BYTES;
        #pragma unroll
        for (int ks = 0; ks < 2; ++ks) {
            const int kb = ks * 32;
            uint32_t ah[4][4], al[4][4], bh[4][2];
            #pragma unroll
            for (int mt = 0; mt < 4; ++mt) {
                const uint32_t ra =
                    db + (wr * 64 + mt * 16 + aRow) * ROWB + kb + aColB;
                ldm_x4(ah[mt], ra);
                ldm_x4(al[mt], ra + TILE_BYTES);
            }
            #pragma unroll
            for (int ntp = 0; ntp < 2; ++ntp) {
                uint32_t B4h[4];
                const uint32_t rb = db + 2 * TILE_BYTES +
                    (wc * 32 + ntp * 16 + aRow) * ROWB + kb + aColB;
                ldm_x4(B4h, rb);
                bh[2 * ntp][0] = B4h[0]; bh[2 * ntp][1] = B4h[2];
                bh[2 * ntp + 1][0] = B4h[1]; bh[2 * ntp + 1][1] = B4h[3];
            }
            #pragma unroll
            for (int mt = 0; mt < 4; ++mt)
                #pragma unroll
                for (int nt = 0; nt < 4; ++nt) {
                    mma_hf(acc[mt][nt], ah[mt], bh[nt]);
                    mma_hf(acc[mt][nt], al[mt], bh[nt]);
                }
        }
        __syncthreads();
        if (s + 2 < NSTG) issue(s + 2);
    }
    __syncthreads();

    float* smf = (float*)smem;
    #pragma unroll
    for (int mt = 0; mt < 4; ++mt)
        #pragma unroll
        for (int nt = 0; nt < 4; ++nt) {
            const int r0 = wr * 64 + mt * 16 + (lane >> 2);
            const int c0 = wc * 32 + nt * 8 + (lane & 3) * 2;
            *(float2*)&smf[r0 * 132 + c0] =
                make_float2(acc[mt][nt][0], acc[mt][nt][1]);
            *(float2*)&smf[(r0 + 8) * 132 + c0] =
                make_float2(acc[mt][nt][2], acc[mt][nt][3]);
        }
    __syncthreads();
}

// ---------------------------------------------------------------------------
// Input projection: writes fp16 hi/lo planes (q,k,v)
// ---------------------------------------------------------------------------
__global__ __launch_bounds__(256, 2) void tc_inproj(const float* __restrict__ bias)
{
    extern __shared__ char smem[];
    const int z = blockIdx.z;
    const int m0 = blockIdx.y * 128, n0 = blockIdx.x * 128;

    mma_mainloop(g_xh + (size_t)z * TB * E_DIM, g_xl + (size_t)z * TB * E_DIM,
                 g_wh + (size_t)z * E_DIM * E_DIM,
                 m0, n0, smem);

    const float* bz = bias + z * E_DIM;
    hf* ph = (z == 0) ? g_qh : ((z == 1) ? g_kh : g_vh);
    hf* pl = (z == 0) ? g_ql : ((z == 1) ? g_kl : g_vl);

    const int tid = threadIdx.x;
    const int row = tid >> 1, seg = tid & 1;
    const int m = m0 + row;
    const int t = m >> 1, b = m & 1;
    const int nb = n0 + seg * 64;
    const int h = nb >> 6;
    const size_t base = ((size_t)(b * H_NUM + h) * T_LEN + t) * D_DIM;
    const float* src = (const float*)smem + row * 132 + seg * 64;
    #pragma unroll
    for (int j = 0; j < 16; ++j) {
        float4 v = *(const float4*)(src + j * 4);
        v.x += bz[nb + j * 4 + 0];
        v.y += bz[nb + j * 4 + 1];
        v.z += bz[nb + j * 4 + 2];
        v.w += bz[nb + j * 4 + 3];
        uint2 H, L;
        split4(v, H, L);
        *(uint2*)(ph + base + j * 4) = H;
        *(uint2*)(pl + base + j * 4) = L;
    }
}

// ---------------------------------------------------------------------------
// Output projection: out = attn @ Wo^T + bo
// ---------------------------------------------------------------------------
__global__ __launch_bounds__(256, 2) void tc_outproj(
    const float* __restrict__ bias, float* __restrict__ out)
{
    extern __shared__ char smem[];
    const int m0 = blockIdx.y * 128, n0 = blockIdx.x * 128;

    mma_mainloop(g_ah, g_al,
                 g_wh + (size_t)3 * E_DIM * E_DIM,
                 m0, n0, smem);

    const int tid = threadIdx.x;
    const int row = tid >> 1, seg = tid & 1;
    const int m = m0 + row;
    const int nb = n0 + seg * 64;
    float* dst = out + (size_t)m * E_DIM + nb;
    const float* src = (const float*)smem + row * 132 + seg * 64;
    #pragma unroll
    for (int j = 0; j < 16; ++j) {
        float4 v = *(const float4*)(src + j * 4);
        v.x += bias[nb + j * 4 + 0];
        v.y += bias[nb + j * 4 + 1];
        v.z += bias[nb + j * 4 + 2];
        v.w += bias[nb + j * 4 + 3];
        *(float4*)(dst + j * 4) = v;
    }
}

// ---------------------------------------------------------------------------
// Fused Pass A+B: per (n-slice, head) walk chunks serially; mma accumulates
// KV in fp32 C-fragments; the exclusive prefix S is written from the
// accumulator BEFORE each chunk's accumulate. Removes g_kvc + scan kernel.
// grid (4, BHN); 8 warps = 4 (mr: m16 of d_k) x 2 (nsub: n8 of d_v).
// ---------------------------------------------------------------------------
#define KS2 144                            // K plane row stride
#define VS2 48                             // V slice row stride (32B + 16 pad)
#define KV2_KH 0
#define KV2_KL (128 * KS2)
#define KV2_VH (2 * 128 * KS2)
#define KV2_VL (KV2_VH + 128 * VS2)
#define KV2_STAGE (KV2_VL + 128 * VS2)     // 49152
#define KV2_SMEM (2 * KV2_STAGE)           // 98304

__global__ __launch_bounds__(256, 1) void kvchunk_scan()
{
    extern __shared__ char smem[];
    const int nq = blockIdx.x;             // 0..3: 16-col slice of d_v
    const int bh = blockIdx.y;
    const int tid = threadIdx.x, lane = tid & 31, w = tid >> 5;
    const int mr = w & 3, nsub = w >> 2;
    const uint32_t smb = smem_u32(smem);

    const size_t hbase = (size_t)bh * T_LEN * D_DIM;

    auto issue = [&](int c) {
        const uint32_t db = smb + (c & 1) * KV2_STAGE;
        const size_t pb = hbase + (size_t)c * CH * D_DIM;
        // K hi/lo: full 128 rows x 128B
        #pragma unroll
        for (int u = 0; u < 4; ++u) {
            const int ci = tid + 256 * u;          // 0..1023
            const int row = ci >> 3, ch = (ci & 7) * 16;
            cp16(db + KV2_KH + row * KS2 + ch, (const char*)(g_kh + pb) + row * 128 + ch);
            cp16(db + KV2_KL + row * KS2 + ch, (const char*)(g_kl + pb) + row * 128 + ch);
        }
        // V hi/lo: 128 rows x 32B slice (cols nq*16 .. +16)
        {
            const int row = tid >> 1, seg = (tid & 1) * 16;
            cp16(db + KV2_VH + row * VS2 + seg, (const char*)(g_vh + pb) + row * 128 + nq * 32 + seg);
            cp16(db + KV2_VL + row * VS2 + seg, (const char*)(g_vl + pb) + row * 128 + nq * 32 + seg);
        }
        CP_COMMIT();
    };

    // K^T (A) trans addressing — verified mapping from kvchunk_mma
    const int aTrow = (lane & 7) + ((lane >> 4) & 1) * 8;
    const int aTcol = mr * 32 + ((lane >> 3) & 1) * 16;
    // V (B) x2 trans addressing: lanes 0-15 give rows, col byte = nsub*16
    const int bTrow = lane & 15;
    const int bTcolB = nsub * 16;

    const int r0 = mr * 16 + (lane >> 2);
    const int colg = nq * 16 + nsub * 8 + (lane & 3) * 2;

    float acc[4] = {0.f, 0.f, 0.f, 0.f};

    issue(0);

    for (int c = 0; c < NC; ++c) {
        if (c + 1 < NC) issue(c + 1);
        if (c + 1 < NC) { CP_WAIT(1); } else { CP_WAIT(0); }
        __syncthreads();

        // exclusive prefix: write current accumulator as S_c (fp16 hi)
        {
            hf* sb = g_sh + (size_t)(bh * NC + c) * (D_DIM * D_DIM);
            *(uint32_t*)(sb + r0 * 64 + colg)       = pk2(acc[0], acc[1]);
            *(uint32_t*)(sb + (r0 + 8) * 64 + colg) = pk2(acc[2], acc[3]);
        }

        const uint32_t db = smb + (c & 1) * KV2_STAGE;
        #pragma unroll
        for (int ks = 0; ks < 8; ++ks) {
            uint32_t ah[4], al[4], b2h[2], b2l[2];
            const uint32_t ra = db + KV2_KH + (ks * 16 + aTrow) * KS2 + aTcol;
            ldm_x4t(ah, ra);
            ldm_x4t(al, ra + (KV2_KL - KV2_KH));
            const uint32_t rb = db + KV2_VH + (ks * 16 + bTrow) * VS2 + bTcolB;
            ldm_x2t(b2h, rb);
            ldm_x2t(b2l, rb + (KV2_VL - KV2_VH));
            mma_hf(acc, ah, b2h);
            mma_hf(acc, ah, b2l);
            mma_hf(acc, al, b2h);
        }
        __syncthreads();
    }
}

// ---------------------------------------------------------------------------
// Pass C (mma): O_c = (Q_c @ S_c + tril(Q_c K_c^T) @ V_c) * scale
// 2-term fp16 (Q hi/lo, P hi/lo; B operands hi only). smem 83KB.
// ---------------------------------------------------------------------------
#define AQS 144
#define SM_QH 0
#define SM_QL (128 * AQS)
#define SM_KH (2 * 128 * AQS)
#define SM_VH (3 * 128 * AQS)
#define SM_SH (4 * 128 * AQS)             // S: 64 rows (k) x 64 cols (v)
#define ATT_SMEM (SM_SH + 64 * AQS)       // 82944 bytes

__global__ __launch_bounds__(256, 1) void attn_mma_kernel()
{
    extern __shared__ char smem[];
    const int c = blockIdx.x, bh = blockIdx.y;
    const int tid = threadIdx.x, lane = tid & 31, w = tid >> 5;
    const uint32_t smb = smem_u32(smem);

    const size_t pbase = (size_t)(bh * T_LEN + c * CH) * D_DIM;
    const char* Qhg = (const char*)(g_qh + pbase);
    const char* Qlg = (const char*)(g_ql + pbase);
    const char* Khg = (const char*)(g_kh + pbase);
    const char* Vhg = (const char*)(g_vh + pbase);

    #pragma unroll
    for (int u = 0; u < 4; ++u) {
        const int ci = tid + 256 * u;
        const int row = ci >> 3, ch = (ci & 7) * 16;
        const int go = row * 128 + ch;
        const uint32_t so = row * AQS + ch;
        cp16(smb + SM_QH + so, Qhg + go);
        cp16(smb + SM_QL + so, Qlg + go);
        cp16(smb + SM_KH + so, Khg + go);
        cp16(smb + SM_VH + so, Vhg + go);
    }
    {
        const char* Shg = (const char*)(g_sh + (size_t)(bh * NC + c) * D_DIM * D_DIM);
        #pragma unroll
        for (int u = 0; u < 2; ++u) {
            const int ci = tid + 256 * u;      // 0..511
            const int row = ci >> 3, ch = (ci & 7) * 16;
            cp16(smb + SM_SH + row * AQS + ch, Shg + row * 128 + ch);
        }
    }
    CP_COMMIT();
    CP_WAIT(0);
    __syncthreads();

    const int aRow = lane & 15;
    const int aColB = (lane >> 4) * 16;

    float oacc[8][4];
    #pragma unroll
    for (int nt = 0; nt < 8; ++nt)
        #pragma unroll
        for (int e = 0; e < 4; ++e) oacc[nt][e] = 0.f;

    float p[16][4];
    #pragma unroll
    for (int nt = 0; nt < 16; ++nt)
        #pragma unroll
        for (int e = 0; e < 4; ++e) p[nt][e] = 0.f;

    // --- Phases 1+2 fused over ks: O += Q@S  and  P = Q K^T (ntp<=w) ---
    #pragma unroll
    for (int ks = 0; ks < 4; ++ks) {
        uint32_t aqh[4], aql[4];
        const uint32_t ra = smb + SM_QH + (w * 16 + aRow) * AQS + ks * 32 + aColB;
        ldm_x4(aqh, ra);
        ldm_x4(aql, ra + (SM_QL - SM_QH));

        #pragma unroll
        for (int ntp = 0; ntp < 4; ++ntp) {
            uint32_t B4h[4];
            const uint32_t rb = smb + SM_SH + (ks * 16 + aRow) * AQS + ntp * 32 + aColB;
            ldm_x4t(B4h, rb);
            mma_hf(oacc[2 * ntp],     aqh, &B4h[0]);
            mma_hf(oacc[2 * ntp],     aql, &B4h[0]);
            mma_hf(oacc[2 * ntp + 1], aqh, &B4h[2]);
            mma_hf(oacc[2 * ntp + 1], aql, &B4h[2]);
        }

        #pragma unroll
        for (int ntp = 0; ntp < 8; ++ntp) {
            if (ntp <= w) {   // causal skip: uniform per warp
                uint32_t B4h[4];
                const uint32_t rb = smb + SM_KH + (ntp * 16 + aRow) * AQS + ks * 32 + aColB;
                ldm_x4(B4h, rb);
                uint32_t bh0[2] = {B4h[0], B4h[2]}, bh1[2] = {B4h[1], B4h[3]};
                mma_hf(p[2 * ntp],     aqh, bh0);
                mma_hf(p[2 * ntp],     aql, bh0);
                mma_hf(p[2 * ntp + 1], aqh, bh1);
                mma_hf(p[2 * ntp + 1], aql, bh1);
            }
        }
    }

    // --- Mask (tril) + pack P into A-fragments (hi/lo) ---
    uint32_t phi[16][2], plo[16][2];
    const int r0 = w * 16 + (lane >> 2);
    const int r1 = r0 + 8;
    #pragma unroll
    for (int nt = 0; nt < 16; ++nt) {
        const int cb = nt * 8 + 2 * (lane & 3);
        float p0 = (cb     <= r0) ? p[nt][0] : 0.f;
        float p1 = (cb + 1 <= r0) ? p[nt][1] : 0.f;
        float p2 = (cb     <= r1) ? p[nt][2] : 0.f;
        float p3 = (cb + 1 <= r1) ? p[nt][3] : 0.f;
        hf h0 = __float2half_rn(p0);
        hf h1 = __float2half_rn(p1);
        hf h2 = __float2half_rn(p2);
        hf h3 = __float2half_rn(p3);
        phi[nt][0] = pk2(__half2float(h0), __half2float(h1));
        phi[nt][1] = pk2(__half2float(h2), __half2float(h3));
        plo[nt][0] = pk2(p0 - __half2float(h0), p1 - __half2float(h1));
        plo[nt][1] = pk2(p2 - __half2float(h2), p3 - __half2float(h3));
    }

    // --- Phase 3: O += P @ V (ks<=w causal skip) ---
    #pragma unroll
    for (int ks = 0; ks < 8; ++ks) {
        if (ks <= w) {
            uint32_t ah[4] = {phi[2 * ks][0], phi[2 * ks][1],
                              phi[2 * ks + 1][0], phi[2 * ks + 1][1]};
            uint32_t al[4] = {plo[2 * ks][0], plo[2 * ks][1],
                              plo[2 * ks + 1][0], plo[2 * ks + 1][1]};
            #pragma unroll
            for (int ntp = 0; ntp < 4; ++ntp) {
                uint32_t B4h[4];
                const uint32_t rb = smb + SM_VH + (ks * 16 + aRow) * AQS + ntp * 32 + aColB;
                ldm_x4t(B4h, rb);
                mma_hf(oacc[2 * ntp],     ah, &B4h[0]);
                mma_hf(oacc[2 * ntp],     al, &B4h[0]);
                mma_hf(oacc[2 * ntp + 1], ah, &B4h[2]);
                mma_hf(oacc[2 * ntp + 1], al, &B4h[2]);
            }
        }
    }

    // --- Epilogue: scale, split hi/lo, write g_ah/g_al at (t*B+b, e) ---
    const int bb = bh / H_NUM, hh = bh % H_NUM;
    #pragma unroll
    for (int nt = 0; nt < 8; ++nt) {
        const int v = nt * 8 + 2 * (lane & 3);
        #pragma unroll
        for (int half = 0; half < 2; ++half) {
            const int i = half ? r1 : r0;
            float o0 = oacc[nt][half * 2 + 0] * SCALE_ATT;
            float o1 = oacc[nt][half * 2 + 1] * SCALE_ATT;
            hf h0 = __float2half_rn(o0);
            hf h1 = __float2half_rn(o1);
            const size_t addr = ((size_t)(c * CH + i) * B_SZ + bb) * E_DIM + hh * 64 + v;
            *(uint32_t*)(g_ah + addr) = pk2(__half2float(h0), __half2float(h1));
            *(uint32_t*)(g_al + addr) = pk2(o0 - __half2float(h0), o1 - __half2float(h1));
        }
    }
}

// ---------------------------------------------------------------------------
extern "C" void kernel_launch(void* const* d_in, const int* in_sizes, int n_in,
                              void* d_out, int out_size)
{
    (void)in_sizes; (void)n_in; (void)out_size;
    const float* query = (const float*)d_in[0];
    const float* key_  = (const float*)d_in[1];
    const float* value = (const float*)d_in[2];
    const float* ipw   = (const float*)d_in[3];
    const float* ipb   = (const float*)d_in[4];
    const float* opw   = (const float*)d_in[5];
    const float* opb   = (const float*)d_in[6];
    float* out = (float*)d_out;

    cudaFuncSetAttribute(tc_inproj,
                         cudaFuncAttributeMaxDynamicSharedMemorySize, GEMM_SMEM);
    cudaFuncSetAttribute(tc_outproj,
                         cudaFuncAttributeMaxDynamicSharedMemorySize, GEMM_SMEM);
    cudaFuncSetAttribute(kvchunk_scan,
                         cudaFuncAttributeMaxDynamicSharedMemorySize, KV2_SMEM);
    cudaFuncSetAttribute(attn_mma_kernel,
                         cudaFuncAttributeMaxDynamicSharedMemorySize, ATT_SMEM);

    split_fused<<<SPLIT_BLOCKS, 256>>>(query, key_, value, ipw, opw);

    tc_inproj<<<dim3(E_DIM / 128, TB / 128, 3), 256, GEMM_SMEM>>>(ipb);

    kvchunk_scan<<<dim3(4, BHN), 256, KV2_SMEM>>>();
    attn_mma_kernel<<<dim3(NC, BHN), 256, ATT_SMEM>>>();

    tc_outproj<<<dim3(E_DIM / 128, TB / 128), 256, GEMM_SMEM>>>(opb, out);
}

// round 13
// speedup vs baseline: 1.0248x; 1.0248x over previous
#include <cuda_runtime.h>
#include <cuda_fp16.h>
#include <cstdint>

// Problem constants
#define T_LEN 1024
#define B_SZ 2
#define E_DIM 1024
#define H_NUM 16
#define D_DIM 64
#define TB (T_LEN * B_SZ)          // 2048
#define CH 128                     // chunk length
#define NC (T_LEN / CH)            // 8 chunks
#define BHN (B_SZ * H_NUM)         // 32 head-batches
#define SCALE_ATT 0.125f           // 1/sqrt(64)

typedef __half hf;

// Scratch (device globals; no allocation allowed)
__device__ float g_kvc[BHN * NC * D_DIM * D_DIM];    // per-chunk K^T V (fp32)

// fp16 planes
__device__ __align__(16) hf g_xh[3 * TB * E_DIM];
__device__ __align__(16) hf g_xl[3 * TB * E_DIM];
__device__ __align__(16) hf g_wh[4 * E_DIM * E_DIM];   // weights: hi only
__device__ __align__(16) hf g_ah[TB * E_DIM];          // attn out (t*B+b, e)
__device__ __align__(16) hf g_al[TB * E_DIM];
// (b,h,t,d) planes for attention
__device__ __align__(16) hf g_qh[BHN * T_LEN * D_DIM];
__device__ __align__(16) hf g_ql[BHN * T_LEN * D_DIM];
__device__ __align__(16) hf g_kh[BHN * T_LEN * D_DIM];
__device__ __align__(16) hf g_kl[BHN * T_LEN * D_DIM];
__device__ __align__(16) hf g_vh[BHN * T_LEN * D_DIM];
__device__ __align__(16) hf g_vl[BHN * T_LEN * D_DIM];
// exclusive-prefix S plane (hi only; k rows, v cols, per chunk)
__device__ __align__(16) hf g_sh[BHN * NC * D_DIM * D_DIM];

// ---- mma.sync helpers --------------------------------------------------------
__device__ __forceinline__ uint32_t smem_u32(const void* p) {
    uint32_t a;
    asm("{ .reg .u64 t; cvta.to.shared.u64 t, %1; cvt.u32.u64 %0, t; }"
        : "=r"(a) : "l"(p));
    return a;
}
__device__ __forceinline__ void cp16(uint32_t dst, const void* src) {
    asm volatile("cp.async.ca.shared.global [%0], [%1], 16;"
                 :: "r"(dst), "l"(src) : "memory");
}
#define CP_COMMIT() asm volatile("cp.async.commit_group;" ::: "memory")
#define CP_WAIT(n)  asm volatile("cp.async.wait_group %0;" :: "n"(n) : "memory")

__device__ __forceinline__ void ldm_x4(uint32_t* r, uint32_t addr) {
    asm volatile("ldmatrix.sync.aligned.m8n8.x4.shared.b16 {%0,%1,%2,%3}, [%4];"
                 : "=r"(r[0]), "=r"(r[1]), "=r"(r[2]), "=r"(r[3]) : "r"(addr));
}
__device__ __forceinline__ void ldm_x4t(uint32_t* r, uint32_t addr) {
    asm volatile("ldmatrix.sync.aligned.m8n8.x4.trans.shared.b16 {%0,%1,%2,%3}, [%4];"
                 : "=r"(r[0]), "=r"(r[1]), "=r"(r[2]), "=r"(r[3]) : "r"(addr));
}
__device__ __forceinline__ void mma_hf(float* c, const uint32_t* a, const uint32_t* b) {
    asm volatile(
        "mma.sync.aligned.m16n8k16.row.col.f32.f16.f16.f32 "
        "{%0,%1,%2,%3}, {%4,%5,%6,%7}, {%8,%9}, {%0,%1,%2,%3};"
        : "+f"(c[0]), "+f"(c[1]), "+f"(c[2]), "+f"(c[3])
        : "r"(a[0]), "r"(a[1]), "r"(a[2]), "r"(a[3]), "r"(b[0]), "r"(b[1]));
}
__device__ __forceinline__ uint32_t pk2(float lo, float hi) {
    __half2 t = __floats2half2_rn(lo, hi);
    return *(uint32_t*)&t;
}
__device__ __forceinline__ void split4(float4 x, uint2& H, uint2& L) {
    union { hf b[4]; uint2 u; } Hu, Lu;
    Hu.b[0] = __float2half_rn(x.x); Lu.b[0] = __float2half_rn(x.x - __half2float(Hu.b[0]));
    Hu.b[1] = __float2half_rn(x.y); Lu.b[1] = __float2half_rn(x.y - __half2float(Hu.b[1]));
    Hu.b[2] = __float2half_rn(x.z); Lu.b[2] = __float2half_rn(x.z - __half2float(Hu.b[2]));
    Hu.b[3] = __float2half_rn(x.w); Lu.b[3] = __float2half_rn(x.w - __half2float(Hu.b[3]));
    H = Hu.u; L = Lu.u;
}
__device__ __forceinline__ uint2 hi4(float4 x) {
    union { hf b[4]; uint2 u; } Hu;
    Hu.b[0] = __float2half_rn(x.x);
    Hu.b[1] = __float2half_rn(x.y);
    Hu.b[2] = __float2half_rn(x.z);
    Hu.b[3] = __float2half_rn(x.w);
    return Hu.u;
}

// ---------------------------------------------------------------------------
// Fused split: activations -> hi/lo, weights -> hi only. 4 float4 / thread.
// ---------------------------------------------------------------------------
#define ACT_F4 (TB * E_DIM / 4)            // 524288
#define W_F4 (E_DIM * E_DIM / 4)           // 262144
#define SPLIT_BLOCKS ((3 * ACT_F4 + 4 * W_F4) / 1024)   // 2560

__global__ __launch_bounds__(256) void split_fused(
    const float* __restrict__ q, const float* __restrict__ k,
    const float* __restrict__ v, const float* __restrict__ ipw,
    const float* __restrict__ opw)
{
    const int blk = blockIdx.x;
    const int tid = threadIdx.x;
    const size_t g0 = (size_t)blk * 1024;

    if (blk < 1536) {
        const int z = blk >> 9;
        const float* src = (z == 0) ? q : ((z == 1) ? k : v);
        const size_t local0 = g0 - (size_t)z * ACT_F4;
        hf* hi = g_xh + (size_t)z * TB * E_DIM;
        hf* lo = g_xl + (size_t)z * TB * E_DIM;
        float4 x[4];
        #pragma unroll
        for (int u = 0; u < 4; ++u)
            x[u] = ((const float4*)src)[local0 + tid + 256 * u];
        #pragma unroll
        for (int u = 0; u < 4; ++u) {
            uint2 H, L;
            split4(x[u], H, L);
            const size_t o = (local0 + tid + 256 * u) * 4;
            *(uint2*)(hi + o) = H;
            *(uint2*)(lo + o) = L;
        }
    } else {
        const float* src;
        size_t local0;
        hf* hi;
        if (blk < 2304) {
            src = ipw;
            local0 = g0 - (size_t)3 * ACT_F4;
            hi = g_wh;
        } else {
            src = opw;
            local0 = g0 - (size_t)3 * ACT_F4 - (size_t)3 * W_F4;
            hi = g_wh + (size_t)3 * E_DIM * E_DIM;
        }
        float4 x[4];
        #pragma unroll
        for (int u = 0; u < 4; ++u)
            x[u] = ((const float4*)src)[local0 + tid + 256 * u];
        #pragma unroll
        for (int u = 0; u < 4; ++u) {
            const size_t o = (local0 + tid + 256 * u) * 4;
            *(uint2*)(hi + o) = hi4(x[u]);
        }
    }
}

// ---------------------------------------------------------------------------
// GEMM mainloop: D(128x128) = A @ B^T.  2-term fp16: Ah*Bh + Al*Bh.
// 2-stage cp.async pipeline (R9-proven config; GEMM is mma-issue-bound).
// ---------------------------------------------------------------------------
#define KC 32
#define ROWB 80
#define TILE_BYTES (128 * ROWB)
#define STAGE_BYTES (3 * TILE_BYTES)       // 30720 (Ah|Al|Bh)
#define GEMM_SMEM 67584                    // max(2*STAGE_BYTES, 128*132*4)
#define NSTG (E_DIM / KC)                  // 32

__device__ __forceinline__ void mma_mainloop(
    const hf* __restrict__ Ah, const hf* __restrict__ Al,
    const hf* __restrict__ Bh,
    int m0, int n0, char* smem)
{
    const int tid = threadIdx.x, lane = tid & 31, wid = tid >> 5;
    const int wr = wid >> 2, wc = wid & 3;
    const uint32_t smb = smem_u32(smem);

    const hf* Ahb = Ah + (size_t)m0 * E_DIM;
    const hf* Alb = Al + (size_t)m0 * E_DIM;
    const hf* Bhb = Bh + (size_t)n0 * E_DIM;

    float acc[4][4][4];
    #pragma unroll
    for (int a = 0; a < 4; ++a)
        #pragma unroll
        for (int b = 0; b < 4; ++b)
            #pragma unroll
            for (int c = 0; c < 4; ++c) acc[a][b][c] = 0.f;

    auto issue = [&](int s) {
        const uint32_t db = smb + (s & 1) * STAGE_BYTES;
        #pragma unroll
        for (int u = 0; u < 2; ++u) {
            const int ci = tid + 256 * u;
            const int row = ci >> 2, kc = ci & 3;
            const uint32_t doff = row * ROWB + kc * 16;
            const size_t soff = (size_t)row * E_DIM + s * KC + kc * 8;
            cp16(db + doff,                  Ahb + soff);
            cp16(db + TILE_BYTES + doff,     Alb + soff);
            cp16(db + 2 * TILE_BYTES + doff, Bhb + soff);
        }
        CP_COMMIT();
    };

    const int aRow = lane & 15;
    const int aColB = (lane >> 4) * 16;

    issue(0);
    issue(1);

    for (int s = 0; s < NSTG; ++s) {
        CP_WAIT(1);
        __syncthreads();

        const uint32_t db = smb + (s & 1) * STAGE_BYTES;
        #pragma unroll
        for (int ks = 0; ks < 2; ++ks) {
            const int kb = ks * 32;
            uint32_t ah[4][4], al[4][4], bh[4][2];
            #pragma unroll
            for (int mt = 0; mt < 4; ++mt) {
                const uint32_t ra =
                    db + (wr * 64 + mt * 16 + aRow) * ROWB + kb + aColB;
                ldm_x4(ah[mt], ra);
                ldm_x4(al[mt], ra + TILE_BYTES);
            }
            #pragma unroll
            for (int ntp = 0; ntp < 2; ++ntp) {
                uint32_t B4h[4];
                const uint32_t rb = db + 2 * TILE_BYTES +
                    (wc * 32 + ntp * 16 + aRow) * ROWB + kb + aColB;
                ldm_x4(B4h, rb);
                bh[2 * ntp][0] = B4h[0]; bh[2 * ntp][1] = B4h[2];
                bh[2 * ntp + 1][0] = B4h[1]; bh[2 * ntp + 1][1] = B4h[3];
            }
            #pragma unroll
            for (int mt = 0; mt < 4; ++mt)
                #pragma unroll
                for (int nt = 0; nt < 4; ++nt) {
                    mma_hf(acc[mt][nt], ah[mt], bh[nt]);
                    mma_hf(acc[mt][nt], al[mt], bh[nt]);
                }
        }
        __syncthreads();
        if (s + 2 < NSTG) issue(s + 2);
    }
    __syncthreads();

    float* smf = (float*)smem;
    #pragma unroll
    for (int mt = 0; mt < 4; ++mt)
        #pragma unroll
        for (int nt = 0; nt < 4; ++nt) {
            const int r0 = wr * 64 + mt * 16 + (lane >> 2);
            const int c0 = wc * 32 + nt * 8 + (lane & 3) * 2;
            *(float2*)&smf[r0 * 132 + c0] =
                make_float2(acc[mt][nt][0], acc[mt][nt][1]);
            *(float2*)&smf[(r0 + 8) * 132 + c0] =
                make_float2(acc[mt][nt][2], acc[mt][nt][3]);
        }
    __syncthreads();
}

// ---------------------------------------------------------------------------
// Input projection: writes fp16 hi/lo planes (q,k,v)
// ---------------------------------------------------------------------------
__global__ __launch_bounds__(256, 2) void tc_inproj(const float* __restrict__ bias)
{
    extern __shared__ char smem[];
    const int z = blockIdx.z;
    const int m0 = blockIdx.y * 128, n0 = blockIdx.x * 128;

    mma_mainloop(g_xh + (size_t)z * TB * E_DIM, g_xl + (size_t)z * TB * E_DIM,
                 g_wh + (size_t)z * E_DIM * E_DIM,
                 m0, n0, smem);

    const float* bz = bias + z * E_DIM;
    hf* ph = (z == 0) ? g_qh : ((z == 1) ? g_kh : g_vh);
    hf* pl = (z == 0) ? g_ql : ((z == 1) ? g_kl : g_vl);

    const int tid = threadIdx.x;
    const int row = tid >> 1, seg = tid & 1;
    const int m = m0 + row;
    const int t = m >> 1, b = m & 1;
    const int nb = n0 + seg * 64;
    const int h = nb >> 6;
    const size_t base = ((size_t)(b * H_NUM + h) * T_LEN + t) * D_DIM;
    const float* src = (const float*)smem + row * 132 + seg * 64;
    #pragma unroll
    for (int j = 0; j < 16; ++j) {
        float4 v = *(const float4*)(src + j * 4);
        v.x += bz[nb + j * 4 + 0];
        v.y += bz[nb + j * 4 + 1];
        v.z += bz[nb + j * 4 + 2];
        v.w += bz[nb + j * 4 + 3];
        uint2 H, L;
        split4(v, H, L);
        *(uint2*)(ph + base + j * 4) = H;
        *(uint2*)(pl + base + j * 4) = L;
    }
}

// ---------------------------------------------------------------------------
// Output projection: out = attn @ Wo^T + bo
// ---------------------------------------------------------------------------
__global__ __launch_bounds__(256, 2) void tc_outproj(
    const float* __restrict__ bias, float* __restrict__ out)
{
    extern __shared__ char smem[];
    const int m0 = blockIdx.y * 128, n0 = blockIdx.x * 128;

    mma_mainloop(g_ah, g_al,
                 g_wh + (size_t)3 * E_DIM * E_DIM,
                 m0, n0, smem);

    const int tid = threadIdx.x;
    const int row = tid >> 1, seg = tid & 1;
    const int m = m0 + row;
    const int nb = n0 + seg * 64;
    float* dst = out + (size_t)m * E_DIM + nb;
    const float* src = (const float*)smem + row * 132 + seg * 64;
    #pragma unroll
    for (int j = 0; j < 16; ++j) {
        float4 v = *(const float4*)(src + j * 4);
        v.x += bias[nb + j * 4 + 0];
        v.y += bias[nb + j * 4 + 1];
        v.z += bias[nb + j * 4 + 2];
        v.w += bias[nb + j * 4 + 3];
        *(float4*)(dst + j * 4) = v;
    }
}

// ---------------------------------------------------------------------------
// Pass A (mma): KV_c = K_c^T V_c (64x64 fp32); 3-term fp16 (accuracy-critical)
// ---------------------------------------------------------------------------
#define KVS 144
#define KV_KH 0
#define KV_KL (128 * KVS)
#define KV_VH (2 * 128 * KVS)
#define KV_VL (3 * 128 * KVS)
#define KV_SMEM (4 * 128 * KVS)            // 73728

__global__ __launch_bounds__(256, 2) void kvchunk_mma()
{
    extern __shared__ char smem[];
    const int c = blockIdx.x, bh = blockIdx.y;
    const int tid = threadIdx.x, lane = tid & 31, w = tid >> 5;
    const int mr = w & 3, nh = w >> 2;
    const uint32_t smb = smem_u32(smem);

    const size_t pbase = (size_t)(bh * T_LEN + c * CH) * D_DIM;
    const char* Khg = (const char*)(g_kh + pbase);
    const char* Klg = (const char*)(g_kl + pbase);
    const char* Vhg = (const char*)(g_vh + pbase);
    const char* Vlg = (const char*)(g_vl + pbase);

    #pragma unroll
    for (int u = 0; u < 4; ++u) {
        const int ci = tid + 256 * u;       // 0..1023
        const int row = ci >> 3, ch = (ci & 7) * 16;
        const int go = row * 128 + ch;
        const uint32_t so = row * KVS + ch;
        cp16(smb + KV_KH + so, Khg + go);
        cp16(smb + KV_KL + so, Klg + go);
        cp16(smb + KV_VH + so, Vhg + go);
        cp16(smb + KV_VL + so, Vlg + go);
    }
    CP_COMMIT();
    CP_WAIT(0);
    __syncthreads();

    float acc[4][4];
    #pragma unroll
    for (int nt = 0; nt < 4; ++nt)
        #pragma unroll
        for (int e = 0; e < 4; ++e) acc[nt][e] = 0.f;

    const int aTrow = (lane & 7) + ((lane >> 4) & 1) * 8;
    const int aTcol = mr * 32 + ((lane >> 3) & 1) * 16;
    const int bTrow = lane & 15;
    const int bTcol = (lane >> 4) * 16;

    #pragma unroll
    for (int ks = 0; ks < 8; ++ks) {
        uint32_t ah[4], al[4];
        const uint32_t ra = smb + KV_KH + (ks * 16 + aTrow) * KVS + aTcol;
        ldm_x4t(ah, ra);
        ldm_x4t(al, ra + (KV_KL - KV_KH));
        #pragma unroll
        for (int ntp = 0; ntp < 2; ++ntp) {
            uint32_t B4h[4], B4l[4];
            const uint32_t rb = smb + KV_VH + (ks * 16 + bTrow) * KVS +
                                nh * 64 + ntp * 32 + bTcol;
            ldm_x4t(B4h, rb);
            ldm_x4t(B4l, rb + (KV_VL - KV_VH));
            mma_hf(acc[2 * ntp],     ah, &B4h[0]);
            mma_hf(acc[2 * ntp],     ah, &B4l[0]);
            mma_hf(acc[2 * ntp],     al, &B4h[0]);
            mma_hf(acc[2 * ntp + 1], ah, &B4h[2]);
            mma_hf(acc[2 * ntp + 1], ah, &B4l[2]);
            mma_hf(acc[2 * ntp + 1], al, &B4h[2]);
        }
    }

    float* outp = g_kvc + (size_t)(bh * NC + c) * D_DIM * D_DIM;
    const int r0 = mr * 16 + (lane >> 2);
    #pragma unroll
    for (int nt = 0; nt < 4; ++nt) {
        const int col = nh * 32 + nt * 8 + (lane & 3) * 2;
        *(float2*)&outp[r0 * 64 + col] = make_float2(acc[nt][0], acc[nt][1]);
        *(float2*)&outp[(r0 + 8) * 64 + col] = make_float2(acc[nt][2], acc[nt][3]);
    }
}

// ---------------------------------------------------------------------------
// Pass B: exclusive prefix-sum over chunks; prefetched; S-hi only
// ---------------------------------------------------------------------------
__global__ __launch_bounds__(256) void scan_kernel()
{
    const int bh = blockIdx.y;
    const int e4 = blockIdx.x * 256 + threadIdx.x;   // 0..1023

    float4 kv[NC];
    #pragma unroll
    for (int c = 0; c < NC; ++c)
        kv[c] = *(const float4*)(g_kvc +
                 (size_t)(bh * NC + c) * (D_DIM * D_DIM) + e4 * 4);

    float4 s = make_float4(0.f, 0.f, 0.f, 0.f);
    #pragma unroll
    for (int c = 0; c < NC; ++c) {
        const size_t idx = (size_t)(bh * NC + c) * (D_DIM * D_DIM) + e4 * 4;
        *(uint2*)(g_sh + idx) = hi4(s);
        s.x += kv[c].x; s.y += kv[c].y; s.z += kv[c].z; s.w += kv[c].w;
    }
}

// ---------------------------------------------------------------------------
// Pass C (mma): O_c = (Q_c @ S_c + tril(Q_c K_c^T) @ V_c) * scale
// 2-term fp16. Mask+pack fused into phase 3 (no phi/plo arrays) to cut
// registers below 128 -> 2 CTAs/SM.
// ---------------------------------------------------------------------------
#define AQS 144
#define SM_QH 0
#define SM_QL (128 * AQS)
#define SM_KH (2 * 128 * AQS)
#define SM_VH (3 * 128 * AQS)
#define SM_SH (4 * 128 * AQS)             // S: 64 rows (k) x 64 cols (v)
#define ATT_SMEM (SM_SH + 64 * AQS)       // 82944 bytes

__global__ __launch_bounds__(256, 2) void attn_mma_kernel()
{
    extern __shared__ char smem[];
    const int c = blockIdx.x, bh = blockIdx.y;
    const int tid = threadIdx.x, lane = tid & 31, w = tid >> 5;
    const uint32_t smb = smem_u32(smem);

    const size_t pbase = (size_t)(bh * T_LEN + c * CH) * D_DIM;
    const char* Qhg = (const char*)(g_qh + pbase);
    const char* Qlg = (const char*)(g_ql + pbase);
    const char* Khg = (const char*)(g_kh + pbase);
    const char* Vhg = (const char*)(g_vh + pbase);

    #pragma unroll
    for (int u = 0; u < 4; ++u) {
        const int ci = tid + 256 * u;
        const int row = ci >> 3, ch = (ci & 7) * 16;
        const int go = row * 128 + ch;
        const uint32_t so = row * AQS + ch;
        cp16(smb + SM_QH + so, Qhg + go);
        cp16(smb + SM_QL + so, Qlg + go);
        cp16(smb + SM_KH + so, Khg + go);
        cp16(smb + SM_VH + so, Vhg + go);
    }
    {
        const char* Shg = (const char*)(g_sh + (size_t)(bh * NC + c) * D_DIM * D_DIM);
        #pragma unroll
        for (int u = 0; u < 2; ++u) {
            const int ci = tid + 256 * u;      // 0..511
            const int row = ci >> 3, ch = (ci & 7) * 16;
            cp16(smb + SM_SH + row * AQS + ch, Shg + row * 128 + ch);
        }
    }
    CP_COMMIT();
    CP_WAIT(0);
    __syncthreads();

    const int aRow = lane & 15;
    const int aColB = (lane >> 4) * 16;

    float oacc[8][4];
    #pragma unroll
    for (int nt = 0; nt < 8; ++nt)
        #pragma unroll
        for (int e = 0; e < 4; ++e) oacc[nt][e] = 0.f;

    float p[16][4];
    #pragma unroll
    for (int nt = 0; nt < 16; ++nt)
        #pragma unroll
        for (int e = 0; e < 4; ++e) p[nt][e] = 0.f;

    // --- Phases 1+2 fused over ks: O += Q@S  and  P = Q K^T (ntp<=w) ---
    #pragma unroll
    for (int ks = 0; ks < 4; ++ks) {
        uint32_t aqh[4], aql[4];
        const uint32_t ra = smb + SM_QH + (w * 16 + aRow) * AQS + ks * 32 + aColB;
        ldm_x4(aqh, ra);
        ldm_x4(aql, ra + (SM_QL - SM_QH));

        #pragma unroll
        for (int ntp = 0; ntp < 4; ++ntp) {
            uint32_t B4h[4];
            const uint32_t rb = smb + SM_SH + (ks * 16 + aRow) * AQS + ntp * 32 + aColB;
            ldm_x4t(B4h, rb);
            mma_hf(oacc[2 * ntp],     aqh, &B4h[0]);
            mma_hf(oacc[2 * ntp],     aql, &B4h[0]);
            mma_hf(oacc[2 * ntp + 1], aqh, &B4h[2]);
            mma_hf(oacc[2 * ntp + 1], aql, &B4h[2]);
        }

        #pragma unroll
        for (int ntp = 0; ntp < 8; ++ntp) {
            if (ntp <= w) {   // causal skip: uniform per warp
                uint32_t B4h[4];
                const uint32_t rb = smb + SM_KH + (ntp * 16 + aRow) * AQS + ks * 32 + aColB;
                ldm_x4(B4h, rb);
                uint32_t bh0[2] = {B4h[0], B4h[2]}, bh1[2] = {B4h[1], B4h[3]};
                mma_hf(p[2 * ntp],     aqh, bh0);
                mma_hf(p[2 * ntp],     aql, bh0);
                mma_hf(p[2 * ntp + 1], aqh, bh1);
                mma_hf(p[2 * ntp + 1], aql, bh1);
            }
        }
    }

    // --- Phase 3: O += P @ V; mask + pack fused per ks (no phi/plo arrays) ---
    const int r0 = w * 16 + (lane >> 2);
    const int r1 = r0 + 8;
    #pragma unroll
    for (int ks = 0; ks < 8; ++ks) {
        if (ks <= w) {
            uint32_t ah[4], al[4];
            #pragma unroll
            for (int j = 0; j < 2; ++j) {
                const int nt = 2 * ks + j;
                const int cb = nt * 8 + 2 * (lane & 3);
                float p0 = (cb     <= r0) ? p[nt][0] : 0.f;
                float p1 = (cb + 1 <= r0) ? p[nt][1] : 0.f;
                float p2 = (cb     <= r1) ? p[nt][2] : 0.f;
                float p3 = (cb + 1 <= r1) ? p[nt][3] : 0.f;
                hf h0 = __float2half_rn(p0);
                hf h1 = __float2half_rn(p1);
                hf h2 = __float2half_rn(p2);
                hf h3 = __float2half_rn(p3);
                ah[2 * j]     = pk2(__half2float(h0), __half2float(h1));
                ah[2 * j + 1] = pk2(__half2float(h2), __half2float(h3));
                al[2 * j]     = pk2(p0 - __half2float(h0), p1 - __half2float(h1));
                al[2 * j + 1] = pk2(p2 - __half2float(h2), p3 - __half2float(h3));
            }
            #pragma unroll
            for (int ntp = 0; ntp < 4; ++ntp) {
                uint32_t B4h[4];
                const uint32_t rb = smb + SM_VH + (ks * 16 + aRow) * AQS + ntp * 32 + aColB;
                ldm_x4t(B4h, rb);
                mma_hf(oacc[2 * ntp],     ah, &B4h[0]);
                mma_hf(oacc[2 * ntp],     al, &B4h[0]);
                mma_hf(oacc[2 * ntp + 1], ah, &B4h[2]);
                mma_hf(oacc[2 * ntp + 1], al, &B4h[2]);
            }
        }
    }

    // --- Epilogue: scale, split hi/lo, write g_ah/g_al at (t*B+b, e) ---
    const int bb = bh / H_NUM, hh = bh % H_NUM;
    #pragma unroll
    for (int nt = 0; nt < 8; ++nt) {
        const int v = nt * 8 + 2 * (lane & 3);
        #pragma unroll
        for (int half = 0; half < 2; ++half) {
            const int i = half ? r1 : r0;
            float o0 = oacc[nt][half * 2 + 0] * SCALE_ATT;
            float o1 = oacc[nt][half * 2 + 1] * SCALE_ATT;
            hf h0 = __float2half_rn(o0);
            hf h1 = __float2half_rn(o1);
            const size_t addr = ((size_t)(c * CH + i) * B_SZ + bb) * E_DIM + hh * 64 + v;
            *(uint32_t*)(g_ah + addr) = pk2(__half2float(h0), __half2float(h1));
            *(uint32_t*)(g_al + addr) = pk2(o0 - __half2float(h0), o1 - __half2float(h1));
        }
    }
}

// ---------------------------------------------------------------------------
extern "C" void kernel_launch(void* const* d_in, const int* in_sizes, int n_in,
                              void* d_out, int out_size)
{
    (void)in_sizes; (void)n_in; (void)out_size;
    const float* query = (const float*)d_in[0];
    const float* key_  = (const float*)d_in[1];
    const float* value = (const float*)d_in[2];
    const float* ipw   = (const float*)d_in[3];
    const float* ipb   = (const float*)d_in[4];
    const float* opw   = (const float*)d_in[5];
    const float* opb   = (const float*)d_in[6];
    float* out = (float*)d_out;

    cudaFuncSetAttribute(tc_inproj,
                         cudaFuncAttributeMaxDynamicSharedMemorySize, GEMM_SMEM);
    cudaFuncSetAttribute(tc_outproj,
                         cudaFuncAttributeMaxDynamicSharedMemorySize, GEMM_SMEM);
    cudaFuncSetAttribute(kvchunk_mma,
                         cudaFuncAttributeMaxDynamicSharedMemorySize, KV_SMEM);
    cudaFuncSetAttribute(attn_mma_kernel,
                         cudaFuncAttributeMaxDynamicSharedMemorySize, ATT_SMEM);

    split_fused<<<SPLIT_BLOCKS, 256>>>(query, key_, value, ipw, opw);

    tc_inproj<<<dim3(E_DIM / 128, TB / 128, 3), 256, GEMM_SMEM>>>(ipb);

    kvchunk_mma<<<dim3(NC, BHN), 256, KV_SMEM>>>();
    scan_kernel<<<dim3(4, BHN), 256>>>();
    attn_mma_kernel<<<dim3(NC, BHN), 256, ATT_SMEM>>>();

    tc_outproj<<<dim3(E_DIM / 128, TB / 128), 256, GEMM_SMEM>>>(opb, out);
}